// round 5
// baseline (speedup 1.0000x reference)
#include <cuda_runtime.h>
#include <cuda_bf16.h>

// Problem constants
#define PB    32    // batch
#define NN    8     // objects
#define P0    64
#define P1    128
#define P2    64
#define CC    128   // channels
#define KK    56    // permutations of (8,2)
#define NT    512   // threads per block (4 groups x 128 channels)
#define GRID  129   // 112 binary + 16 unary + 1 nullary (single wave on 148 SMs)

// Scratch (allocation-free: __device__ globals)
__device__ float g_N0[PB * CC];
__device__ float g_U0[PB * NN * CC];
__device__ float g_U1[PB * NN * CC];
__device__ float g_B0[PB * KK * CC];
__device__ float g_B1[PB * KK * CC];
__device__ int   g_arrive;   // zero-init; self-reset each launch
__device__ int   g_done;

// tanh(x) = 1 - 2/(exp(2x)+1). Safe at large |x|.
__device__ __forceinline__ float fast_tanh(float x) {
    const float e = __expf(2.0f * x);
    return 1.0f - __fdividef(2.0f, e + 1.0f);
}

__global__ __launch_bounds__(NT) void fused_k(const float* __restrict__ nullary,
                                              const float* __restrict__ unary,
                                              const float* __restrict__ binary,
                                              const float* __restrict__ kern,
                                              float* __restrict__ out) {
    const int blk = blockIdx.x;
    const int tid = threadIdx.x;
    const int g   = tid >> 7;     // batch group 0..3
    const int c   = tid & 127;    // channel
    const int bg  = g * 8;        // group batch base

    __shared__ float xs[4096];    // 16 KB x staging (max: unary 32x128)

    // ---------------- Phase 1: slot-partial mins ----------------
    if (blk < 112) {
        // binary slots: one pair m, groups split 32 batches, 64 features
        const bool slot1 = (blk >= 56);
        const int  m     = slot1 ? blk - 56 : blk;
        const int  i     = m / 7;
        const int  jp    = m % 7;
        const int  tbase = slot1 ? 384 : 320;

        for (int idx = tid; idx < PB * P2; idx += NT) {
            const int b = idx >> 6, f = idx & 63;
            xs[idx] = binary[((b * NN + i) * (NN - 1) + jp) * P2 + f];
        }
        __syncthreads();

        float acc[8];
        #pragma unroll
        for (int b = 0; b < 8; b++) acc[b] = 1e30f;

        const float* krow = kern + tbase * CC + c;
        #pragma unroll 4
        for (int f = 0; f < P2; f++) {
            const float t = fast_tanh(krow[f * CC]);
            const float q = fmaf(-t, t, 1.0f);
            #pragma unroll
            for (int b = 0; b < 8; b++)
                acc[b] = fminf(acc[b], fmaf(xs[((bg + b) << 6) + f], t, q));
        }

        float* dst = slot1 ? g_B1 : g_B0;
        #pragma unroll
        for (int b = 0; b < 8; b++)
            dst[((bg + b) * KK + m) * CC + c] = acc[b];

    } else if (blk < 128) {
        // unary slots: one object i, one slot; groups split 32 batches, 128 features
        const int  r     = blk - 112;
        const bool slot1 = (r >= 8);
        const int  i     = r & 7;
        const int  tbase = slot1 ? 192 : 64;

        for (int idx = tid; idx < PB * P1; idx += NT) {
            const int b = idx >> 7, f = idx & 127;
            xs[idx] = unary[(b * NN + i) * P1 + f];
        }
        __syncthreads();

        float acc[8];
        #pragma unroll
        for (int b = 0; b < 8; b++) acc[b] = 1e30f;

        const float* krow = kern + tbase * CC + c;
        #pragma unroll 4
        for (int f = 0; f < P1; f++) {
            const float t = fast_tanh(krow[f * CC]);
            const float q = fmaf(-t, t, 1.0f);
            #pragma unroll
            for (int b = 0; b < 8; b++)
                acc[b] = fminf(acc[b], fmaf(xs[((bg + b) << 7) + f], t, q));
        }

        float* dst = slot1 ? g_U1 : g_U0;
        #pragma unroll
        for (int b = 0; b < 8; b++)
            dst[((bg + b) * NN + i) * CC + c] = acc[b];

    } else {
        // nullary slot: groups split 32 batches, 64 features
        for (int idx = tid; idx < PB * P0; idx += NT) {
            const int b = idx >> 6, f = idx & 63;
            xs[idx] = nullary[b * P0 + f];
        }
        __syncthreads();

        float acc[8];
        #pragma unroll
        for (int b = 0; b < 8; b++) acc[b] = 1e30f;

        const float* krow = kern + c;
        #pragma unroll 4
        for (int f = 0; f < P0; f++) {
            const float t = fast_tanh(krow[f * CC]);
            const float q = fmaf(-t, t, 1.0f);
            #pragma unroll
            for (int b = 0; b < 8; b++)
                acc[b] = fminf(acc[b], fmaf(xs[((bg + b) << 6) + f], t, q));
        }

        #pragma unroll
        for (int b = 0; b < 8; b++)
            g_N0[(bg + b) * CC + c] = acc[b];
    }

    // ---------------- Grid soft-barrier (single wave: 129 blocks <= 148 SMs) ----------------
    __threadfence();
    __syncthreads();
    if (tid == 0) atomicAdd(&g_arrive, 1);

    if (blk >= PB) return;   // only blocks 0..31 combine

    if (tid == 0) {
        while (*((volatile int*)&g_arrive) != GRID) { }
    }
    __syncthreads();
    __threadfence();

    // ---------------- Phase 2: combine for batch b = blk (threads 0..127) ----------------
    if (tid < CC) {
        const int b = blk;
        float u0[NN], u1[NN];
        #pragma unroll
        for (int i = 0; i < NN; i++) {
            u0[i] = g_U0[(b * NN + i) * CC + c];
            u1[i] = g_U1[(b * NN + i) * CC + c];
        }
        const float n0 = g_N0[b * CC + c];

        float mx = -1e30f;
        #pragma unroll
        for (int k = 0; k < KK; k++) {
            const int i  = k / 7;
            const int r  = k % 7;
            const int j  = r + (r >= i);
            const int rv = j * 7 + (i - (i > j));  // reversed-pair index
            const float b0v = g_B0[(b * KK + k)  * CC + c];
            const float b1v = g_B1[(b * KK + rv) * CC + c];
            float v = fminf(fminf(b0v, b1v), fminf(u0[i], u1[j]));
            v = fminf(v, n0);
            mx = fmaxf(mx, v);
        }
        out[b * CC + c] = mx;
    }

    // ---------------- Counter reset for graph replay ----------------
    __syncthreads();
    if (tid == 0) {
        const int old = atomicAdd(&g_done, 1);
        if (old == PB - 1) {
            atomicExch(&g_arrive, 0);
            atomicExch(&g_done, 0);
        }
    }
}

extern "C" void kernel_launch(void* const* d_in, const int* in_sizes, int n_in,
                              void* d_out, int out_size) {
    const float* nullary = (const float*)d_in[0];  // (32, 64)
    const float* unary   = (const float*)d_in[1];  // (32, 8, 128)
    const float* binary  = (const float*)d_in[2];  // (32, 8, 7, 64)
    const float* kern    = (const float*)d_in[3];  // (448, 128)
    float* out = (float*)d_out;                    // (32, 128)

    fused_k<<<GRID, NT>>>(nullary, unary, binary, kern, out);
}

// round 6
// speedup vs baseline: 1.1875x; 1.1875x over previous
#include <cuda_runtime.h>
#include <cuda_bf16.h>

// Problem constants
#define PB    32    // batch
#define NN    8     // objects
#define P0    64
#define P1    128
#define P2    64
#define CC    128   // channels
#define KK    56    // permutations of (8,2)
#define NT    512   // threads per block
#define GRID  145   // 112 binary + 32 unary + 1 nullary (single wave on 148 SMs)
#define PASSF 32    // tanh rows per pass staged in smem

// Scratch (allocation-free: __device__ globals)
__device__ float g_N0[PB * CC];
__device__ float g_U0[PB * NN * CC];
__device__ float g_U1[PB * NN * CC];
__device__ float g_B0[PB * KK * CC];
__device__ float g_B1[PB * KK * CC];
__device__ int   g_arrive;   // zero-init; self-reset each launch
__device__ int   g_done;

// tanh(x) = 1 - 2/(exp(2x)+1). Safe at large |x|.
__device__ __forceinline__ float fast_tanh(float x) {
    const float e = __expf(2.0f * x);
    return 1.0f - __fdividef(2.0f, e + 1.0f);
}

__global__ __launch_bounds__(NT) void fused_k(const float* __restrict__ nullary,
                                              const float* __restrict__ unary,
                                              const float* __restrict__ binary,
                                              const float* __restrict__ kern,
                                              float* __restrict__ out) {
    const int blk = blockIdx.x;
    const int tid = threadIdx.x;
    const int g   = tid >> 7;     // group 0..3
    const int c   = tid & 127;    // channel

    __shared__ __align__(16) float  xs[2048];          // 8 KB  x staging
    __shared__ __align__(16) float2 tq[PASSF * CC];    // 32 KB (t, 1-t^2) per pass
    const float2* xs2 = reinterpret_cast<const float2*>(xs);

    // ================= Phase 1: slot-partial mins =================
    if (blk < 112) {
        // ---- binary slots: one pair m, 32 batches x 64 features; A=8 per thread ----
        const bool slot1 = (blk >= 56);
        const int  m     = slot1 ? blk - 56 : blk;
        const int  i     = m / 7;
        const int  jp    = m % 7;
        const int  tbase = slot1 ? 384 : 320;
        const int  bg    = g * 8;

        for (int idx = tid; idx < PB * P2; idx += NT) {
            const int b = idx >> 6, f = idx & 63;
            xs[idx] = binary[((b * NN + i) * (NN - 1) + jp) * P2 + f];
        }

        float acc[8];
        #pragma unroll
        for (int b = 0; b < 8; b++) acc[b] = 1e30f;

        #pragma unroll
        for (int pass = 0; pass < P2 / PASSF; pass++) {
            __syncthreads();
            for (int idx = tid; idx < PASSF * CC; idx += NT) {
                const float t = fast_tanh(kern[(tbase + pass * PASSF + (idx >> 7)) * CC + (idx & 127)]);
                tq[idx] = make_float2(t, fmaf(-t, t, 1.0f));
            }
            __syncthreads();

            const int fh = (pass * PASSF) >> 1;
            #pragma unroll 8
            for (int f2 = 0; f2 < PASSF / 2; f2++) {
                const float2 ta = tq[(2 * f2) * CC + c];
                const float2 tb = tq[(2 * f2 + 1) * CC + c];
                #pragma unroll
                for (int b = 0; b < 8; b++) {
                    const float2 x2 = xs2[(bg + b) * 32 + fh + f2];
                    acc[b] = fminf(acc[b], fmaf(x2.x, ta.x, ta.y));
                    acc[b] = fminf(acc[b], fmaf(x2.y, tb.x, tb.y));
                }
            }
        }

        float* dst = slot1 ? g_B1 : g_B0;
        #pragma unroll
        for (int b = 0; b < 8; b++)
            dst[((bg + b) * KK + m) * CC + c] = acc[b];

    } else if (blk < 144) {
        // ---- unary slots: one (i, slot, batch-half); 16 batches x 128 features; A=4 ----
        const int  r     = blk - 112;
        const bool slot1 = (r >= 16);
        const int  rr    = r & 15;
        const int  i     = rr >> 1;
        const int  b0    = (rr & 1) * 16;
        const int  tbase = slot1 ? 192 : 64;
        const int  bg    = g * 4;

        for (int idx = tid; idx < 16 * P1; idx += NT) {
            const int b = idx >> 7, f = idx & 127;
            xs[idx] = unary[((b0 + b) * NN + i) * P1 + f];
        }

        float acc[4];
        #pragma unroll
        for (int b = 0; b < 4; b++) acc[b] = 1e30f;

        #pragma unroll
        for (int pass = 0; pass < P1 / PASSF; pass++) {
            __syncthreads();
            for (int idx = tid; idx < PASSF * CC; idx += NT) {
                const float t = fast_tanh(kern[(tbase + pass * PASSF + (idx >> 7)) * CC + (idx & 127)]);
                tq[idx] = make_float2(t, fmaf(-t, t, 1.0f));
            }
            __syncthreads();

            const int fh = (pass * PASSF) >> 1;
            #pragma unroll 8
            for (int f2 = 0; f2 < PASSF / 2; f2++) {
                const float2 ta = tq[(2 * f2) * CC + c];
                const float2 tb = tq[(2 * f2 + 1) * CC + c];
                #pragma unroll
                for (int b = 0; b < 4; b++) {
                    const float2 x2 = xs2[(bg + b) * 64 + fh + f2];
                    acc[b] = fminf(acc[b], fmaf(x2.x, ta.x, ta.y));
                    acc[b] = fminf(acc[b], fmaf(x2.y, tb.x, tb.y));
                }
            }
        }

        float* dst = slot1 ? g_U1 : g_U0;
        #pragma unroll
        for (int b = 0; b < 4; b++)
            dst[((b0 + bg + b) * NN + i) * CC + c] = acc[b];

    } else {
        // ---- nullary slot: 32 batches x 64 features; A=8 ----
        const int bg = g * 8;

        for (int idx = tid; idx < PB * P0; idx += NT) {
            const int b = idx >> 6, f = idx & 63;
            xs[idx] = nullary[b * P0 + f];
        }

        float acc[8];
        #pragma unroll
        for (int b = 0; b < 8; b++) acc[b] = 1e30f;

        #pragma unroll
        for (int pass = 0; pass < P0 / PASSF; pass++) {
            __syncthreads();
            for (int idx = tid; idx < PASSF * CC; idx += NT) {
                const float t = fast_tanh(kern[(pass * PASSF + (idx >> 7)) * CC + (idx & 127)]);
                tq[idx] = make_float2(t, fmaf(-t, t, 1.0f));
            }
            __syncthreads();

            const int fh = (pass * PASSF) >> 1;
            #pragma unroll 8
            for (int f2 = 0; f2 < PASSF / 2; f2++) {
                const float2 ta = tq[(2 * f2) * CC + c];
                const float2 tb = tq[(2 * f2 + 1) * CC + c];
                #pragma unroll
                for (int b = 0; b < 8; b++) {
                    const float2 x2 = xs2[(bg + b) * 32 + fh + f2];
                    acc[b] = fminf(acc[b], fmaf(x2.x, ta.x, ta.y));
                    acc[b] = fminf(acc[b], fmaf(x2.y, tb.x, tb.y));
                }
            }
        }

        #pragma unroll
        for (int b = 0; b < 8; b++)
            g_N0[(bg + b) * CC + c] = acc[b];
    }

    // ================= Grid soft-barrier (145 blocks, single wave) =================
    __threadfence();
    __syncthreads();
    if (tid == 0) atomicAdd(&g_arrive, 1);

    if (blk >= PB) return;   // only blocks 0..31 combine

    if (tid == 0) {
        while (*((volatile int*)&g_arrive) != GRID) { }
    }
    __syncthreads();
    __threadfence();

    // ================= Phase 2: combine for batch b = blk =================
    {
        const int b = blk;
        float u0[NN], u1[NN];
        #pragma unroll
        for (int ii = 0; ii < NN; ii++) {
            u0[ii] = g_U0[(b * NN + ii) * CC + c];
            u1[ii] = g_U1[(b * NN + ii) * CC + c];
        }
        const float n0 = g_N0[b * CC + c];

        // group g handles k in [g*14, g*14+14)
        float mx = -1e30f;
        const int k0 = g * 14;
        #pragma unroll
        for (int kk = 0; kk < 14; kk++) {
            const int k  = k0 + kk;
            const int i  = k / 7;
            const int r  = k % 7;
            const int j  = r + (r >= i);
            const int rv = j * 7 + (i - (i > j));  // reversed-pair index
            const float b0v = g_B0[(b * KK + k)  * CC + c];
            const float b1v = g_B1[(b * KK + rv) * CC + c];
            float v = fminf(fminf(b0v, b1v), fminf(u0[i], u1[j]));
            v = fminf(v, n0);
            mx = fmaxf(mx, v);
        }
        xs[g * CC + c] = mx;
        __syncthreads();
        if (tid < CC) {
            float m = fmaxf(fmaxf(xs[c], xs[CC + c]),
                            fmaxf(xs[2 * CC + c], xs[3 * CC + c]));
            out[b * CC + c] = m;
        }
    }

    // ================= Counter reset for graph replay =================
    __syncthreads();
    if (tid == 0) {
        const int old = atomicAdd(&g_done, 1);
        if (old == PB - 1) {
            atomicExch(&g_arrive, 0);
            atomicExch(&g_done, 0);
        }
    }
}

extern "C" void kernel_launch(void* const* d_in, const int* in_sizes, int n_in,
                              void* d_out, int out_size) {
    const float* nullary = (const float*)d_in[0];  // (32, 64)
    const float* unary   = (const float*)d_in[1];  // (32, 8, 128)
    const float* binary  = (const float*)d_in[2];  // (32, 8, 7, 64)
    const float* kern    = (const float*)d_in[3];  // (448, 128)
    float* out = (float*)d_out;                    // (32, 128)

    fused_k<<<GRID, NT>>>(nullary, unary, binary, kern, out);
}